// round 16
// baseline (speedup 1.0000x reference)
#include <cuda_runtime.h>
#include <cuda_fp16.h>
#include <cstdint>

#define HEADS 8
#define DMODEL 640
#define SEQ 2048
#define BATCH 4
#define HD 80
#define M_TOT 8192      // BATCH*SEQ
#define NKV 1920        // 3*DMODEL

// ---- scratch (device globals) ----
__device__ __half g_wqkv_h[NKV * DMODEL];
__device__ __half g_wqkv_l[NKV * DMODEL];
__device__ __half g_wo_h[DMODEL * DMODEL];
__device__ __half g_wo_l[DMODEL * DMODEL];
__device__ __half g_xh[M_TOT * DMODEL];
__device__ __half g_xl[M_TOT * DMODEL];
__device__ __half g_qh[BATCH * HEADS * SEQ * HD];
__device__ __half g_ql[BATCH * HEADS * SEQ * HD];
__device__ __half g_kh[BATCH * HEADS * SEQ * HD];
__device__ __half g_kl[BATCH * HEADS * SEQ * HD];
__device__ float  g_v [BATCH * HEADS * SEQ * HD];
__device__ __half g_vth[BATCH * HEADS * HD * SEQ];   // transposed [bh][d][s], hi only
__device__ __half g_ah[M_TOT * DMODEL];              // attn out (fp16 hi only)

// ============================================================
// primitives
// ============================================================
__device__ __forceinline__ uint32_t smem_u32(const void* p) {
    uint32_t a;
    asm("{ .reg .u64 t; cvta.to.shared.u64 t, %1; cvt.u32.u64 %0, t; }" : "=r"(a) : "l"(p));
    return a;
}
#define CP16(dst, src) \
    asm volatile("cp.async.cg.shared.global [%0], [%1], 16;" :: "r"(dst), "l"(src) : "memory")
#define CP_COMMIT() asm volatile("cp.async.commit_group;" ::: "memory")
#define CP_WAIT1()  asm volatile("cp.async.wait_group 1;" ::: "memory")
#define CP_WAIT0()  asm volatile("cp.async.wait_group 0;" ::: "memory")

__device__ __forceinline__ void mma_f16(float d[4], const uint32_t a[4], const uint32_t b[2]) {
    asm volatile(
        "mma.sync.aligned.m16n8k16.row.col.f32.f16.f16.f32 "
        "{%0,%1,%2,%3}, {%4,%5,%6,%7}, {%8,%9}, {%0,%1,%2,%3};"
        : "+f"(d[0]), "+f"(d[1]), "+f"(d[2]), "+f"(d[3])
        : "r"(a[0]), "r"(a[1]), "r"(a[2]), "r"(a[3]), "r"(b[0]), "r"(b[1]));
}

// pack two fp32 into half2 hi + half2 lo (Markidis split)
__device__ __forceinline__ void split2(float a, float b, uint32_t& h, uint32_t& l) {
    __half2 hh = __floats2half2_rn(a, b);
    float2 hf = __half22float2(hh);
    __half2 ll = __floats2half2_rn(a - hf.x, b - hf.y);
    h = *(uint32_t*)&hh;
    l = *(uint32_t*)&ll;
}
__device__ __forceinline__ uint32_t pack2(float a, float b) {
    __half2 hh = __floats2half2_rn(a, b);
    return *(uint32_t*)&hh;
}

// ============================================================
// 1) prep: fold LoRA -> hi/lo fp16 weights; x -> hi/lo fp16
// ============================================================
__global__ void prep_kernel(const float* __restrict__ x,
                            const float* __restrict__ wq, const float* __restrict__ wk,
                            const float* __restrict__ wv, const float* __restrict__ wo,
                            const float* __restrict__ qd, const float* __restrict__ qu,
                            const float* __restrict__ kd, const float* __restrict__ ku,
                            const float* __restrict__ vd, const float* __restrict__ vu,
                            const float* __restrict__ od, const float* __restrict__ ou)
{
    int idx = blockIdx.x * blockDim.x + threadIdx.x;
    const int TQKV = NKV * DMODEL;
    const int TO = DMODEL * DMODEL;
    const int TX = M_TOT * DMODEL;
    if (idx < TQKV) {
        int n = idx / DMODEL, k = idx - n * DMODEL;
        int which = n / DMODEL;
        int nn = n - which * DMODEL;
        const float* W  = (which == 0) ? wq : (which == 1) ? wk : wv;
        const float* up = (which == 0) ? qu : (which == 1) ? ku : vu;
        const float* dn = (which == 0) ? qd : (which == 1) ? kd : vd;
        float v = W[nn * DMODEL + k];
#pragma unroll
        for (int r = 0; r < 4; r++) v += up[nn * 4 + r] * dn[r * DMODEL + k];
        __half h = __float2half_rn(v);
        g_wqkv_h[idx] = h;
        g_wqkv_l[idx] = __float2half_rn(v - __half2float(h));
    } else if (idx < TQKV + TO) {
        int j = idx - TQKV;
        int n = j / DMODEL, k = j - n * DMODEL;
        float v = wo[n * DMODEL + k];
#pragma unroll
        for (int r = 0; r < 4; r++) v += ou[n * 4 + r] * od[r * DMODEL + k];
        __half h = __float2half_rn(v);
        g_wo_h[j] = h;
        g_wo_l[j] = __float2half_rn(v - __half2float(h));
    } else if (idx < TQKV + TO + TX) {
        int j = idx - TQKV - TO;
        float v = x[j];
        __half h = __float2half_rn(v);
        g_xh[j] = h;
        g_xl[j] = __float2half_rn(v - __half2float(h));
    }
}

// ============================================================
// fp16-split projection GEMM core; nterms = 2 or 3 split MMAs
// ============================================================
#define ASTRh 40
#define CHUNKh (128 * ASTRh)                 // 5120 halves/array/buffer
#define GEMM_SMEM (2 * 4 * CHUNKh * 2)       // 81920 B

__device__ __forceinline__ void proj_issue(const __half* __restrict__ Ah,
                                           const __half* __restrict__ Al,
                                           const __half* __restrict__ Bh,
                                           const __half* __restrict__ Bl,
                                           int m0, int n0, int kc, int buf,
                                           uint32_t sb, int tid)
{
#pragma unroll
    for (int i = 0; i < 8; i++) {
        int idx = tid + i * 256;            // 0..2047
        int arr = idx >> 9;                 // 0..3
        int w = idx & 511;
        int row = w >> 2, c = w & 3;
        const __half* src = (arr == 0) ? Ah : (arr == 1) ? Al : (arr == 2) ? Bh : Bl;
        int rb = (arr < 2) ? m0 : n0;
        uint32_t dst = sb + (uint32_t)(buf * 4 * CHUNKh + arr * CHUNKh + row * ASTRh + c * 8) * 2;
        CP16(dst, src + (long)(rb + row) * DMODEL + kc * 32 + c * 8);
    }
    CP_COMMIT();
}

__device__ __forceinline__ void proj_mainloop(const __half* __restrict__ Ah,
                                              const __half* __restrict__ Al,
                                              const __half* __restrict__ Bh,
                                              const __half* __restrict__ Bl,
                                              int m0, int n0, __half* smem,
                                              float acc[4][4][4], int nterms)
{
    int tid = threadIdx.x, lane = tid & 31, wid = tid >> 5;
    int g = lane >> 2, q = lane & 3;
    int wm = wid & 1, wn = wid >> 1;
    uint32_t sb = smem_u32(smem);

    proj_issue(Ah, Al, Bh, Bl, m0, n0, 0, 0, sb, tid);
    for (int c = 0; c < 20; c++) {
        int buf = c & 1;
        if (c < 19) { proj_issue(Ah, Al, Bh, Bl, m0, n0, c + 1, buf ^ 1, sb, tid); CP_WAIT1(); }
        else        { CP_WAIT0(); }
        __syncthreads();
        const __half* As_h = smem + buf * 4 * CHUNKh;
        const __half* As_l = As_h + CHUNKh;
        const __half* Bs_h = As_h + 2 * CHUNKh;
        const __half* Bs_l = As_h + 3 * CHUNKh;
#pragma unroll
        for (int k16 = 0; k16 < 2; k16++) {
            uint32_t ah[4][4], al[4][4];
#pragma unroll
            for (int mi = 0; mi < 4; mi++) {
                const __half* p  = As_h + (wm * 64 + mi * 16 + g) * ASTRh + k16 * 16 + q * 2;
                const __half* pl = As_l + (wm * 64 + mi * 16 + g) * ASTRh + k16 * 16 + q * 2;
                ah[mi][0] = *(const uint32_t*)p;
                ah[mi][1] = *(const uint32_t*)(p + 8 * ASTRh);
                ah[mi][2] = *(const uint32_t*)(p + 8);
                ah[mi][3] = *(const uint32_t*)(p + 8 * ASTRh + 8);
                al[mi][0] = *(const uint32_t*)pl;
                al[mi][1] = *(const uint32_t*)(pl + 8 * ASTRh);
                al[mi][2] = *(const uint32_t*)(pl + 8);
                al[mi][3] = *(const uint32_t*)(pl + 8 * ASTRh + 8);
            }
#pragma unroll
            for (int ni = 0; ni < 4; ni++) {
                const __half* pb  = Bs_h + (wn * 32 + ni * 8 + g) * ASTRh + k16 * 16 + q * 2;
                const __half* pbl = Bs_l + (wn * 32 + ni * 8 + g) * ASTRh + k16 * 16 + q * 2;
                uint32_t bh[2], bl[2];
                bh[0] = *(const uint32_t*)pb;  bh[1] = *(const uint32_t*)(pb + 8);
                bl[0] = *(const uint32_t*)pbl; bl[1] = *(const uint32_t*)(pbl + 8);
#pragma unroll
                for (int mi = 0; mi < 4; mi++) {
                    mma_f16(acc[mi][ni], ah[mi], bh);
                    mma_f16(acc[mi][ni], ah[mi], bl);
                    if (nterms == 3) mma_f16(acc[mi][ni], al[mi], bh);
                }
            }
        }
        __syncthreads();
    }
}

// ---- QKV GEMM: scatter epilogue -> Q/K hi-lo fp16, V fp32, [B,H,S,hd] ----
// V column-blocks (blockIdx.x >= 10) use 2-term split: V is consumed as
// fp16-hi by PV anyway, so the x_lo refinement is below its later rounding.
__global__ void __launch_bounds__(256) gemm_qkv_mma()
{
    extern __shared__ __half smem[];
    int n0 = blockIdx.x * 128, m0 = blockIdx.y * 128;
    float acc[4][4][4] = {};
    int nterms = (blockIdx.x >= 10) ? 2 : 3;
    proj_mainloop(g_xh, g_xl, g_wqkv_h, g_wqkv_l, m0, n0, smem, acc, nterms);

    int tid = threadIdx.x, lane = tid & 31, wid = tid >> 5;
    int g = lane >> 2, q = lane & 3;
    int wm = wid & 1, wn = wid >> 1;
#pragma unroll
    for (int mi = 0; mi < 4; mi++) {
        int r0 = m0 + wm * 64 + mi * 16 + g;
        int bb = r0 >> 11, ss = r0 & 2047;
#pragma unroll
        for (int ni = 0; ni < 4; ni++) {
            int n = n0 + wn * 32 + ni * 8 + 2 * q;
            int which = n / DMODEL;
            int nn = n - which * DMODEL;
            int h = nn / HD, d = nn - h * HD;
            long base = ((long)(bb * HEADS + h) * SEQ + ss) * HD + d;
            if (which == 2) {
                *(float2*)(g_v + base)          = make_float2(acc[mi][ni][0], acc[mi][ni][1]);
                *(float2*)(g_v + base + 8 * HD) = make_float2(acc[mi][ni][2], acc[mi][ni][3]);
            } else {
                __half* Hh = (which == 0) ? g_qh : g_kh;
                __half* Hl = (which == 0) ? g_ql : g_kl;
                uint32_t h2, l2;
                split2(acc[mi][ni][0], acc[mi][ni][1], h2, l2);
                *(uint32_t*)(Hh + base) = h2;
                *(uint32_t*)(Hl + base) = l2;
                split2(acc[mi][ni][2], acc[mi][ni][3], h2, l2);
                *(uint32_t*)(Hh + base + 8 * HD) = h2;
                *(uint32_t*)(Hl + base + 8 * HD) = l2;
            }
        }
    }
}

// ---- O GEMM: A = attn (hi only), B = wo hi/lo, 2-term, +bias, fp32 out ----
__global__ void __launch_bounds__(256) gemm_o_mma(const float* __restrict__ bo,
                                                  float* __restrict__ out)
{
    extern __shared__ __half smem[];
    int n0 = blockIdx.x * 128, m0 = blockIdx.y * 128;
    float acc[4][4][4] = {};
    proj_mainloop(g_ah, g_ah, g_wo_h, g_wo_l, m0, n0, smem, acc, 2);

    int tid = threadIdx.x, lane = tid & 31, wid = tid >> 5;
    int g = lane >> 2, q = lane & 3;
    int wm = wid & 1, wn = wid >> 1;
#pragma unroll
    for (int mi = 0; mi < 4; mi++) {
        int r0 = m0 + wm * 64 + mi * 16 + g;
#pragma unroll
        for (int ni = 0; ni < 4; ni++) {
            int n = n0 + wn * 32 + ni * 8 + 2 * q;
            float b0v = bo[n], b1v = bo[n + 1];
            *(float2*)(out + (long)r0 * DMODEL + n) =
                make_float2(acc[mi][ni][0] + b0v, acc[mi][ni][1] + b1v);
            *(float2*)(out + (long)(r0 + 8) * DMODEL + n) =
                make_float2(acc[mi][ni][2] + b0v, acc[mi][ni][3] + b1v);
        }
    }
}

// ============================================================
// 2b) V transpose (hi only): g_v [bh][s][d] -> g_vth [bh][d][s]
// ============================================================
__global__ void __launch_bounds__(256) vtrans_kernel()
{
    __shared__ float tile[64 * 81];
    int bh = blockIdx.y;
    int sb0 = blockIdx.x * 64;
    int tid = threadIdx.x;
    const float* src = g_v + ((long)bh * SEQ + sb0) * HD;
#pragma unroll
    for (int i = 0; i < 20; i++) {
        int idx = tid + i * 256;
        int r = idx / 80, c = idx - r * 80;
        tile[r * 81 + c] = src[idx];
    }
    __syncthreads();
    __half* dh = g_vth + (long)bh * HD * SEQ + sb0;
#pragma unroll
    for (int i = 0; i < 10; i++) {
        int idx = tid + i * 256;
        int d = idx >> 5, s2 = idx & 31;
        float v0 = tile[(2 * s2) * 81 + d];
        float v1 = tile[(2 * s2 + 1) * 81 + d];
        *(uint32_t*)(dh + (long)d * SEQ + 2 * s2) = pack2(v0, v1);
    }
}

// ============================================================
// 3) Flash attention. BM=64, BN=64, 2 CTAs/SM (R13 config), P in regs.
// QK: 3-term split. PV: single fp16 MMA. Output: fp16 hi only.
// ============================================================
#define KSTRh 88
#define VSh   72
#define KT_SZ (64 * KSTRh)            // 5632
#define VT_SZ (80 * VSh)              // 5760
#define BUF_SZ (2 * KT_SZ + VT_SZ)    // 17024 halves
#define FLASH_SMEM (2 * BUF_SZ * 2)   // 68096 B

__device__ __forceinline__ void flash_issue(const __half* __restrict__ kh,
                                            const __half* __restrict__ kl,
                                            const __half* __restrict__ vth,
                                            int base, int buf, uint32_t sb, int tid)
{
#pragma unroll
    for (int i = 0; i < 15; i++) {
        int idx = tid + i * 128;            // 0..1919
        int arr = idx / 640;                // 0=Kh 1=Kl 2=Vh
        int w = idx - arr * 640;
        uint32_t dst; const __half* src;
        if (arr < 2) {
            int row = w / 10, c = w - row * 10;
            dst = sb + (uint32_t)(buf * BUF_SZ + arr * KT_SZ + row * KSTRh + c * 8) * 2;
            src = ((arr == 0) ? kh : kl) + (long)(base + row) * HD + c * 8;
        } else {
            int row = w >> 3, c = w & 7;
            dst = sb + (uint32_t)(buf * BUF_SZ + 2 * KT_SZ + row * VSh + c * 8) * 2;
            src = vth + (long)row * SEQ + base + c * 8;
        }
        CP16(dst, src);
    }
    CP_COMMIT();
}

__global__ void __launch_bounds__(128, 2) flash_kernel()
{
    extern __shared__ __half smem[];
    int tid = threadIdx.x, lane = tid & 31, wid = tid >> 5;   // wid 0..3
    int g = lane >> 2, q = lane & 3;
    int bh = blockIdx.y, b = bh >> 3, h = bh & 7;
    int s0 = blockIdx.x * 64;
    uint32_t sb = smem_u32(smem);

    const __half* qhg = g_qh + (long)bh * SEQ * HD;
    const __half* qlg = g_ql + (long)bh * SEQ * HD;
    const __half* khg = g_kh + (long)bh * SEQ * HD;
    const __half* klg = g_kl + (long)bh * SEQ * HD;
    const __half* vthg = g_vth + (long)bh * HD * SEQ;

    flash_issue(khg, klg, vthg, 0, 0, sb, tid);

    // Q fragments (hi & lo) in registers: 5 k16 chunks
    uint32_t qfh[5][4], qfl[5][4];
    {
        const __half* r0h = qhg + (long)(s0 + wid * 16 + g) * HD + q * 2;
        const __half* r0l = qlg + (long)(s0 + wid * 16 + g) * HD + q * 2;
#pragma unroll
        for (int k16 = 0; k16 < 5; k16++) {
            qfh[k16][0] = *(const uint32_t*)(r0h + k16 * 16);
            qfh[k16][1] = *(const uint32_t*)(r0h + 8 * HD + k16 * 16);
            qfh[k16][2] = *(const uint32_t*)(r0h + k16 * 16 + 8);
            qfh[k16][3] = *(const uint32_t*)(r0h + 8 * HD + k16 * 16 + 8);
            qfl[k16][0] = *(const uint32_t*)(r0l + k16 * 16);
            qfl[k16][1] = *(const uint32_t*)(r0l + 8 * HD + k16 * 16);
            qfl[k16][2] = *(const uint32_t*)(r0l + k16 * 16 + 8);
            qfl[k16][3] = *(const uint32_t*)(r0l + 8 * HD + k16 * 16 + 8);
        }
    }

    float oacc[10][4] = {};
    float m0p = -1e30f, m1p = -1e30f, l0 = 0.f, l1 = 0.f;
    const float sm_scale = 0.11180339887498948f;   // 1/sqrt(80)

    for (int kt = 0; kt < SEQ / 64; kt++) {
        int buf = kt & 1;
        if (kt < SEQ / 64 - 1) {
            flash_issue(khg, klg, vthg, (kt + 1) * 64, buf ^ 1, sb, tid);
            CP_WAIT1();
        } else CP_WAIT0();
        __syncthreads();

        const __half* Ksh = smem + buf * BUF_SZ;
        const __half* Ksl = Ksh + KT_SZ;
        const __half* Vsh = Ksh + 2 * KT_SZ;

        // S = Q K^T  (warp: 16 x 64), 3-mma split (precision-critical)
        float sacc[8][4] = {};
#pragma unroll
        for (int k16 = 0; k16 < 5; k16++) {
#pragma unroll
            for (int ni = 0; ni < 8; ni++) {
                const __half* pb  = Ksh + (ni * 8 + g) * KSTRh + k16 * 16 + q * 2;
                const __half* pbl = Ksl + (ni * 8 + g) * KSTRh + k16 * 16 + q * 2;
                uint32_t bh2[2], bl2[2];
                bh2[0] = *(const uint32_t*)pb;  bh2[1] = *(const uint32_t*)(pb + 8);
                bl2[0] = *(const uint32_t*)pbl; bl2[1] = *(const uint32_t*)(pbl + 8);
                mma_f16(sacc[ni], qfh[k16], bh2);
                mma_f16(sacc[ni], qfh[k16], bl2);
                mma_f16(sacc[ni], qfl[k16], bh2);
            }
        }

        // online softmax (rows g and g+8, quad shfl reduce); P stays in regs
        float mx0 = -1e30f, mx1 = -1e30f;
#pragma unroll
        for (int ni = 0; ni < 8; ni++) {
            sacc[ni][0] *= sm_scale; sacc[ni][1] *= sm_scale;
            sacc[ni][2] *= sm_scale; sacc[ni][3] *= sm_scale;
            mx0 = fmaxf(mx0, fmaxf(sacc[ni][0], sacc[ni][1]));
            mx1 = fmaxf(mx1, fmaxf(sacc[ni][2], sacc[ni][3]));
        }
        mx0 = fmaxf(mx0, __shfl_xor_sync(0xffffffffu, mx0, 1));
        mx0 = fmaxf(mx0, __shfl_xor_sync(0xffffffffu, mx0, 2));
        mx1 = fmaxf(mx1, __shfl_xor_sync(0xffffffffu, mx1, 1));
        mx1 = fmaxf(mx1, __shfl_xor_sync(0xffffffffu, mx1, 2));
        float mn0 = fmaxf(m0p, mx0), mn1 = fmaxf(m1p, mx1);
        float a0 = __expf(m0p - mn0), a1 = __expf(m1p - mn1);
        float rs0 = 0.f, rs1 = 0.f;
#pragma unroll
        for (int ni = 0; ni < 8; ni++) {
            sacc[ni][0] = __expf(sacc[ni][0] - mn0);
            sacc[ni][1] = __expf(sacc[ni][1] - mn0);
            sacc[ni][2] = __expf(sacc[ni][2] - mn1);
            sacc[ni][3] = __expf(sacc[ni][3] - mn1);
            rs0 += sacc[ni][0] + sacc[ni][1];
            rs1 += sacc[ni][2] + sacc[ni][3];
        }
        rs0 += __shfl_xor_sync(0xffffffffu, rs0, 1);
        rs0 += __shfl_xor_sync(0xffffffffu, rs0, 2);
        rs1 += __shfl_xor_sync(0xffffffffu, rs1, 1);
        rs1 += __shfl_xor_sync(0xffffffffu, rs1, 2);
        l0 = l0 * a0 + rs0; l1 = l1 * a1 + rs1;
        m0p = mn0; m1p = mn1;

        // rescale O accumulators
#pragma unroll
        for (int ni = 0; ni < 10; ni++) {
            oacc[ni][0] *= a0; oacc[ni][1] *= a0;
            oacc[ni][2] *= a1; oacc[ni][3] *= a1;
        }

        // O += P V: single fp16 MMA (hi only) via C->A fragment reuse
#pragma unroll
        for (int c = 0; c < 4; c++) {
            uint32_t pah[4];
            pah[0] = pack2(sacc[2 * c][0],     sacc[2 * c][1]);
            pah[1] = pack2(sacc[2 * c][2],     sacc[2 * c][3]);
            pah[2] = pack2(sacc[2 * c + 1][0], sacc[2 * c + 1][1]);
            pah[3] = pack2(sacc[2 * c + 1][2], sacc[2 * c + 1][3]);
#pragma unroll
            for (int ni = 0; ni < 10; ni++) {
                const __half* pb = Vsh + (ni * 8 + g) * VSh + c * 16 + q * 2;
                uint32_t bh2[2];
                bh2[0] = *(const uint32_t*)pb;  bh2[1] = *(const uint32_t*)(pb + 8);
                mma_f16(oacc[ni], pah, bh2);
            }
        }
        __syncthreads();
    }

    // normalize + write attn (fp16 hi only) [B,S,D]
    float inv0 = 1.f / l0, inv1 = 1.f / l1;
    int r0 = s0 + wid * 16 + g;
    long o0 = (long)(b * SEQ + r0) * DMODEL + h * HD;
    long o1 = o0 + 8 * DMODEL;
#pragma unroll
    for (int ni = 0; ni < 10; ni++) {
        int col = ni * 8 + 2 * q;
        *(uint32_t*)(g_ah + o0 + col) = pack2(oacc[ni][0] * inv0, oacc[ni][1] * inv0);
        *(uint32_t*)(g_ah + o1 + col) = pack2(oacc[ni][2] * inv1, oacc[ni][3] * inv1);
    }
}

// ============================================================
// launch
// ============================================================
extern "C" void kernel_launch(void* const* d_in, const int* in_sizes, int n_in,
                              void* d_out, int out_size)
{
    const float* x  = (const float*)d_in[0];
    const float* wq = (const float*)d_in[1];
    const float* wk = (const float*)d_in[2];
    const float* wv = (const float*)d_in[3];
    const float* wo = (const float*)d_in[4];
    const float* bo = (const float*)d_in[5];
    const float* qd = (const float*)d_in[6];
    const float* qu = (const float*)d_in[7];
    const float* kd = (const float*)d_in[8];
    const float* ku = (const float*)d_in[9];
    const float* vd = (const float*)d_in[10];
    const float* vu = (const float*)d_in[11];
    const float* od = (const float*)d_in[12];
    const float* ou = (const float*)d_in[13];
    float* out = (float*)d_out;

    cudaFuncSetAttribute(gemm_qkv_mma, cudaFuncAttributeMaxDynamicSharedMemorySize, GEMM_SMEM);
    cudaFuncSetAttribute(gemm_o_mma,   cudaFuncAttributeMaxDynamicSharedMemorySize, GEMM_SMEM);
    cudaFuncSetAttribute(flash_kernel, cudaFuncAttributeMaxDynamicSharedMemorySize, FLASH_SMEM);

    {
        int total = NKV * DMODEL + DMODEL * DMODEL + M_TOT * DMODEL;
        prep_kernel<<<(total + 255) / 256, 256>>>(x, wq, wk, wv, wo,
                                                  qd, qu, kd, ku, vd, vu, od, ou);
    }
    {
        dim3 grid(NKV / 128, M_TOT / 128);   // 15 x 64
        gemm_qkv_mma<<<grid, 256, GEMM_SMEM>>>();
    }
    {
        dim3 grid(SEQ / 64, BATCH * HEADS);  // 32 x 32
        vtrans_kernel<<<grid, 256>>>();
    }
    {
        dim3 grid(SEQ / 64, BATCH * HEADS);  // 32 x 32
        flash_kernel<<<grid, 128, FLASH_SMEM>>>();
    }
    {
        dim3 grid(DMODEL / 128, M_TOT / 128); // 5 x 64
        gemm_o_mma<<<grid, 256, GEMM_SMEM>>>(bo, out);
    }
}

// round 17
// speedup vs baseline: 1.5430x; 1.5430x over previous
#include <cuda_runtime.h>
#include <cuda_fp16.h>
#include <cstdint>

#define HEADS 8
#define DMODEL 640
#define SEQ 2048
#define BATCH 4
#define HD 80
#define M_TOT 8192      // BATCH*SEQ
#define NKV 1920        // 3*DMODEL

// ---- scratch (device globals) ----
__device__ __half g_wqkv_h[NKV * DMODEL];
__device__ __half g_wqkv_l[NKV * DMODEL];
__device__ __half g_wo_h[DMODEL * DMODEL];
__device__ __half g_wo_l[DMODEL * DMODEL];
__device__ __half g_xh[M_TOT * DMODEL];
__device__ __half g_xl[M_TOT * DMODEL];
__device__ __half g_qh[BATCH * HEADS * SEQ * HD];
__device__ __half g_ql[BATCH * HEADS * SEQ * HD];
__device__ __half g_kh[BATCH * HEADS * SEQ * HD];
__device__ __half g_kl[BATCH * HEADS * SEQ * HD];
__device__ float  g_v [BATCH * HEADS * SEQ * HD];
__device__ __half g_vth[BATCH * HEADS * HD * SEQ];   // transposed [bh][d][s], hi only
__device__ __half g_ah[M_TOT * DMODEL];              // attn out (fp16 hi only)

// ============================================================
// primitives
// ============================================================
__device__ __forceinline__ uint32_t smem_u32(const void* p) {
    uint32_t a;
    asm("{ .reg .u64 t; cvta.to.shared.u64 t, %1; cvt.u32.u64 %0, t; }" : "=r"(a) : "l"(p));
    return a;
}
#define CP16(dst, src) \
    asm volatile("cp.async.cg.shared.global [%0], [%1], 16;" :: "r"(dst), "l"(src) : "memory")
#define CP_COMMIT() asm volatile("cp.async.commit_group;" ::: "memory")
#define CP_WAIT1()  asm volatile("cp.async.wait_group 1;" ::: "memory")
#define CP_WAIT0()  asm volatile("cp.async.wait_group 0;" ::: "memory")

__device__ __forceinline__ void mma_f16(float d[4], const uint32_t a[4], const uint32_t b[2]) {
    asm volatile(
        "mma.sync.aligned.m16n8k16.row.col.f32.f16.f16.f32 "
        "{%0,%1,%2,%3}, {%4,%5,%6,%7}, {%8,%9}, {%0,%1,%2,%3};"
        : "+f"(d[0]), "+f"(d[1]), "+f"(d[2]), "+f"(d[3])
        : "r"(a[0]), "r"(a[1]), "r"(a[2]), "r"(a[3]), "r"(b[0]), "r"(b[1]));
}

// pack two fp32 into half2 hi + half2 lo (Markidis split)
__device__ __forceinline__ void split2(float a, float b, uint32_t& h, uint32_t& l) {
    __half2 hh = __floats2half2_rn(a, b);
    float2 hf = __half22float2(hh);
    __half2 ll = __floats2half2_rn(a - hf.x, b - hf.y);
    h = *(uint32_t*)&hh;
    l = *(uint32_t*)&ll;
}
__device__ __forceinline__ uint32_t pack2(float a, float b) {
    __half2 hh = __floats2half2_rn(a, b);
    return *(uint32_t*)&hh;
}

// ============================================================
// 1) prep: fold LoRA -> hi/lo fp16 weights; x -> hi/lo fp16
// ============================================================
__global__ void prep_kernel(const float* __restrict__ x,
                            const float* __restrict__ wq, const float* __restrict__ wk,
                            const float* __restrict__ wv, const float* __restrict__ wo,
                            const float* __restrict__ qd, const float* __restrict__ qu,
                            const float* __restrict__ kd, const float* __restrict__ ku,
                            const float* __restrict__ vd, const float* __restrict__ vu,
                            const float* __restrict__ od, const float* __restrict__ ou)
{
    int idx = blockIdx.x * blockDim.x + threadIdx.x;
    const int TQKV = NKV * DMODEL;
    const int TO = DMODEL * DMODEL;
    const int TX = M_TOT * DMODEL;
    if (idx < TQKV) {
        int n = idx / DMODEL, k = idx - n * DMODEL;
        int which = n / DMODEL;
        int nn = n - which * DMODEL;
        const float* W  = (which == 0) ? wq : (which == 1) ? wk : wv;
        const float* up = (which == 0) ? qu : (which == 1) ? ku : vu;
        const float* dn = (which == 0) ? qd : (which == 1) ? kd : vd;
        float v = W[nn * DMODEL + k];
#pragma unroll
        for (int r = 0; r < 4; r++) v += up[nn * 4 + r] * dn[r * DMODEL + k];
        __half h = __float2half_rn(v);
        g_wqkv_h[idx] = h;
        g_wqkv_l[idx] = __float2half_rn(v - __half2float(h));
    } else if (idx < TQKV + TO) {
        int j = idx - TQKV;
        int n = j / DMODEL, k = j - n * DMODEL;
        float v = wo[n * DMODEL + k];
#pragma unroll
        for (int r = 0; r < 4; r++) v += ou[n * 4 + r] * od[r * DMODEL + k];
        __half h = __float2half_rn(v);
        g_wo_h[j] = h;
        g_wo_l[j] = __float2half_rn(v - __half2float(h));
    } else if (idx < TQKV + TO + TX) {
        int j = idx - TQKV - TO;
        float v = x[j];
        __half h = __float2half_rn(v);
        g_xh[j] = h;
        g_xl[j] = __float2half_rn(v - __half2float(h));
    }
}

// ============================================================
// fp16-split projection GEMM core; nterms = 2 or 3 split MMAs
// ============================================================
#define ASTRh 40
#define CHUNKh (128 * ASTRh)                 // 5120 halves/array/buffer
#define GEMM_SMEM (2 * 4 * CHUNKh * 2)       // 81920 B

__device__ __forceinline__ void proj_issue(const __half* __restrict__ Ah,
                                           const __half* __restrict__ Al,
                                           const __half* __restrict__ Bh,
                                           const __half* __restrict__ Bl,
                                           int m0, int n0, int kc, int buf,
                                           uint32_t sb, int tid)
{
#pragma unroll
    for (int i = 0; i < 8; i++) {
        int idx = tid + i * 256;            // 0..2047
        int arr = idx >> 9;                 // 0..3
        int w = idx & 511;
        int row = w >> 2, c = w & 3;
        const __half* src = (arr == 0) ? Ah : (arr == 1) ? Al : (arr == 2) ? Bh : Bl;
        int rb = (arr < 2) ? m0 : n0;
        uint32_t dst = sb + (uint32_t)(buf * 4 * CHUNKh + arr * CHUNKh + row * ASTRh + c * 8) * 2;
        CP16(dst, src + (long)(rb + row) * DMODEL + kc * 32 + c * 8);
    }
    CP_COMMIT();
}

__device__ __forceinline__ void proj_mainloop(const __half* __restrict__ Ah,
                                              const __half* __restrict__ Al,
                                              const __half* __restrict__ Bh,
                                              const __half* __restrict__ Bl,
                                              int m0, int n0, __half* smem,
                                              float acc[4][4][4], int nterms)
{
    int tid = threadIdx.x, lane = tid & 31, wid = tid >> 5;
    int g = lane >> 2, q = lane & 3;
    int wm = wid & 1, wn = wid >> 1;
    uint32_t sb = smem_u32(smem);

    proj_issue(Ah, Al, Bh, Bl, m0, n0, 0, 0, sb, tid);
    for (int c = 0; c < 20; c++) {
        int buf = c & 1;
        if (c < 19) { proj_issue(Ah, Al, Bh, Bl, m0, n0, c + 1, buf ^ 1, sb, tid); CP_WAIT1(); }
        else        { CP_WAIT0(); }
        __syncthreads();
        const __half* As_h = smem + buf * 4 * CHUNKh;
        const __half* As_l = As_h + CHUNKh;
        const __half* Bs_h = As_h + 2 * CHUNKh;
        const __half* Bs_l = As_h + 3 * CHUNKh;
#pragma unroll
        for (int k16 = 0; k16 < 2; k16++) {
            uint32_t ah[4][4], al[4][4];
#pragma unroll
            for (int mi = 0; mi < 4; mi++) {
                const __half* p  = As_h + (wm * 64 + mi * 16 + g) * ASTRh + k16 * 16 + q * 2;
                const __half* pl = As_l + (wm * 64 + mi * 16 + g) * ASTRh + k16 * 16 + q * 2;
                ah[mi][0] = *(const uint32_t*)p;
                ah[mi][1] = *(const uint32_t*)(p + 8 * ASTRh);
                ah[mi][2] = *(const uint32_t*)(p + 8);
                ah[mi][3] = *(const uint32_t*)(p + 8 * ASTRh + 8);
                al[mi][0] = *(const uint32_t*)pl;
                al[mi][1] = *(const uint32_t*)(pl + 8 * ASTRh);
                al[mi][2] = *(const uint32_t*)(pl + 8);
                al[mi][3] = *(const uint32_t*)(pl + 8 * ASTRh + 8);
            }
#pragma unroll
            for (int ni = 0; ni < 4; ni++) {
                const __half* pb  = Bs_h + (wn * 32 + ni * 8 + g) * ASTRh + k16 * 16 + q * 2;
                const __half* pbl = Bs_l + (wn * 32 + ni * 8 + g) * ASTRh + k16 * 16 + q * 2;
                uint32_t bh[2], bl[2];
                bh[0] = *(const uint32_t*)pb;  bh[1] = *(const uint32_t*)(pb + 8);
                bl[0] = *(const uint32_t*)pbl; bl[1] = *(const uint32_t*)(pbl + 8);
#pragma unroll
                for (int mi = 0; mi < 4; mi++) {
                    mma_f16(acc[mi][ni], ah[mi], bh);
                    mma_f16(acc[mi][ni], ah[mi], bl);
                    if (nterms == 3) mma_f16(acc[mi][ni], al[mi], bh);
                }
            }
        }
        __syncthreads();
    }
}

// ---- QKV GEMM: scatter epilogue -> Q/K hi-lo fp16, V fp32, [B,H,S,hd] ----
// V column-blocks (blockIdx.x >= 10) use 2-term split: V is consumed as
// fp16-hi by PV anyway, so the x_lo refinement is below its later rounding.
__global__ void __launch_bounds__(256) gemm_qkv_mma()
{
    extern __shared__ __half smem[];
    int n0 = blockIdx.x * 128, m0 = blockIdx.y * 128;
    float acc[4][4][4] = {};
    int nterms = (blockIdx.x >= 10) ? 2 : 3;
    proj_mainloop(g_xh, g_xl, g_wqkv_h, g_wqkv_l, m0, n0, smem, acc, nterms);

    int tid = threadIdx.x, lane = tid & 31, wid = tid >> 5;
    int g = lane >> 2, q = lane & 3;
    int wm = wid & 1, wn = wid >> 1;
#pragma unroll
    for (int mi = 0; mi < 4; mi++) {
        int r0 = m0 + wm * 64 + mi * 16 + g;
        int bb = r0 >> 11, ss = r0 & 2047;
#pragma unroll
        for (int ni = 0; ni < 4; ni++) {
            int n = n0 + wn * 32 + ni * 8 + 2 * q;
            int which = n / DMODEL;
            int nn = n - which * DMODEL;
            int h = nn / HD, d = nn - h * HD;
            long base = ((long)(bb * HEADS + h) * SEQ + ss) * HD + d;
            if (which == 2) {
                *(float2*)(g_v + base)          = make_float2(acc[mi][ni][0], acc[mi][ni][1]);
                *(float2*)(g_v + base + 8 * HD) = make_float2(acc[mi][ni][2], acc[mi][ni][3]);
            } else {
                __half* Hh = (which == 0) ? g_qh : g_kh;
                __half* Hl = (which == 0) ? g_ql : g_kl;
                uint32_t h2, l2;
                split2(acc[mi][ni][0], acc[mi][ni][1], h2, l2);
                *(uint32_t*)(Hh + base) = h2;
                *(uint32_t*)(Hl + base) = l2;
                split2(acc[mi][ni][2], acc[mi][ni][3], h2, l2);
                *(uint32_t*)(Hh + base + 8 * HD) = h2;
                *(uint32_t*)(Hl + base + 8 * HD) = l2;
            }
        }
    }
}

// ---- O GEMM: A = attn (hi only), B = wo hi/lo, 2-term, +bias, fp32 out ----
__global__ void __launch_bounds__(256) gemm_o_mma(const float* __restrict__ bo,
                                                  float* __restrict__ out)
{
    extern __shared__ __half smem[];
    int n0 = blockIdx.x * 128, m0 = blockIdx.y * 128;
    float acc[4][4][4] = {};
    proj_mainloop(g_ah, g_ah, g_wo_h, g_wo_l, m0, n0, smem, acc, 2);

    int tid = threadIdx.x, lane = tid & 31, wid = tid >> 5;
    int g = lane >> 2, q = lane & 3;
    int wm = wid & 1, wn = wid >> 1;
#pragma unroll
    for (int mi = 0; mi < 4; mi++) {
        int r0 = m0 + wm * 64 + mi * 16 + g;
#pragma unroll
        for (int ni = 0; ni < 4; ni++) {
            int n = n0 + wn * 32 + ni * 8 + 2 * q;
            float b0v = bo[n], b1v = bo[n + 1];
            *(float2*)(out + (long)r0 * DMODEL + n) =
                make_float2(acc[mi][ni][0] + b0v, acc[mi][ni][1] + b1v);
            *(float2*)(out + (long)(r0 + 8) * DMODEL + n) =
                make_float2(acc[mi][ni][2] + b0v, acc[mi][ni][3] + b1v);
        }
    }
}

// ============================================================
// 2b) V transpose (hi only): g_v [bh][s][d] -> g_vth [bh][d][s]
// ============================================================
__global__ void __launch_bounds__(256) vtrans_kernel()
{
    __shared__ float tile[64 * 81];
    int bh = blockIdx.y;
    int sb0 = blockIdx.x * 64;
    int tid = threadIdx.x;
    const float* src = g_v + ((long)bh * SEQ + sb0) * HD;
#pragma unroll
    for (int i = 0; i < 20; i++) {
        int idx = tid + i * 256;
        int r = idx / 80, c = idx - r * 80;
        tile[r * 81 + c] = src[idx];
    }
    __syncthreads();
    __half* dh = g_vth + (long)bh * HD * SEQ + sb0;
#pragma unroll
    for (int i = 0; i < 10; i++) {
        int idx = tid + i * 256;
        int d = idx >> 5, s2 = idx & 31;
        float v0 = tile[(2 * s2) * 81 + d];
        float v1 = tile[(2 * s2 + 1) * 81 + d];
        *(uint32_t*)(dh + (long)d * SEQ + 2 * s2) = pack2(v0, v1);
    }
}

// ============================================================
// 3) Flash attention. BM=64, BN=64, 2 CTAs/SM (R13 config), P in regs.
// QK: 3-term split. PV: single fp16 MMA. Output: fp16 hi only.
// ============================================================
#define KSTRh 88
#define VSh   72
#define KT_SZ (64 * KSTRh)            // 5632
#define VT_SZ (80 * VSh)              // 5760
#define BUF_SZ (2 * KT_SZ + VT_SZ)    // 17024 halves
#define FLASH_SMEM (2 * BUF_SZ * 2)   // 68096 B

__device__ __forceinline__ void flash_issue(const __half* __restrict__ kh,
                                            const __half* __restrict__ kl,
                                            const __half* __restrict__ vth,
                                            int base, int buf, uint32_t sb, int tid)
{
#pragma unroll
    for (int i = 0; i < 15; i++) {
        int idx = tid + i * 128;            // 0..1919
        int arr = idx / 640;                // 0=Kh 1=Kl 2=Vh
        int w = idx - arr * 640;
        uint32_t dst; const __half* src;
        if (arr < 2) {
            int row = w / 10, c = w - row * 10;
            dst = sb + (uint32_t)(buf * BUF_SZ + arr * KT_SZ + row * KSTRh + c * 8) * 2;
            src = ((arr == 0) ? kh : kl) + (long)(base + row) * HD + c * 8;
        } else {
            int row = w >> 3, c = w & 7;
            dst = sb + (uint32_t)(buf * BUF_SZ + 2 * KT_SZ + row * VSh + c * 8) * 2;
            src = vth + (long)row * SEQ + base + c * 8;
        }
        CP16(dst, src);
    }
    CP_COMMIT();
}

__global__ void __launch_bounds__(128, 2) flash_kernel()
{
    extern __shared__ __half smem[];
    int tid = threadIdx.x, lane = tid & 31, wid = tid >> 5;   // wid 0..3
    int g = lane >> 2, q = lane & 3;
    int bh = blockIdx.y, b = bh >> 3, h = bh & 7;
    int s0 = blockIdx.x * 64;
    uint32_t sb = smem_u32(smem);

    const __half* qhg = g_qh + (long)bh * SEQ * HD;
    const __half* qlg = g_ql + (long)bh * SEQ * HD;
    const __half* khg = g_kh + (long)bh * SEQ * HD;
    const __half* klg = g_kl + (long)bh * SEQ * HD;
    const __half* vthg = g_vth + (long)bh * HD * SEQ;

    flash_issue(khg, klg, vthg, 0, 0, sb, tid);

    // Q fragments (hi & lo) in registers: 5 k16 chunks
    uint32_t qfh[5][4], qfl[5][4];
    {
        const __half* r0h = qhg + (long)(s0 + wid * 16 + g) * HD + q * 2;
        const __half* r0l = qlg + (long)(s0 + wid * 16 + g) * HD + q * 2;
#pragma unroll
        for (int k16 = 0; k16 < 5; k16++) {
            qfh[k16][0] = *(const uint32_t*)(r0h + k16 * 16);
            qfh[k16][1] = *(const uint32_t*)(r0h + 8 * HD + k16 * 16);
            qfh[k16][2] = *(const uint32_t*)(r0h + k16 * 16 + 8);
            qfh[k16][3] = *(const uint32_t*)(r0h + 8 * HD + k16 * 16 + 8);
            qfl[k16][0] = *(const uint32_t*)(r0l + k16 * 16);
            qfl[k16][1] = *(const uint32_t*)(r0l + 8 * HD + k16 * 16);
            qfl[k16][2] = *(const uint32_t*)(r0l + k16 * 16 + 8);
            qfl[k16][3] = *(const uint32_t*)(r0l + 8 * HD + k16 * 16 + 8);
        }
    }

    float oacc[10][4] = {};
    float m0p = -1e30f, m1p = -1e30f, l0 = 0.f, l1 = 0.f;
    const float sm_scale = 0.11180339887498948f;   // 1/sqrt(80)

    for (int kt = 0; kt < SEQ / 64; kt++) {
        int buf = kt & 1;
        if (kt < SEQ / 64 - 1) {
            flash_issue(khg, klg, vthg, (kt + 1) * 64, buf ^ 1, sb, tid);
            CP_WAIT1();
        } else CP_WAIT0();
        __syncthreads();

        const __half* Ksh = smem + buf * BUF_SZ;
        const __half* Ksl = Ksh + KT_SZ;
        const __half* Vsh = Ksh + 2 * KT_SZ;

        // S = Q K^T  (warp: 16 x 64), 3-mma split (precision-critical)
        float sacc[8][4] = {};
#pragma unroll
        for (int k16 = 0; k16 < 5; k16++) {
#pragma unroll
            for (int ni = 0; ni < 8; ni++) {
                const __half* pb  = Ksh + (ni * 8 + g) * KSTRh + k16 * 16 + q * 2;
                const __half* pbl = Ksl + (ni * 8 + g) * KSTRh + k16 * 16 + q * 2;
                uint32_t bh2[2], bl2[2];
                bh2[0] = *(const uint32_t*)pb;  bh2[1] = *(const uint32_t*)(pb + 8);
                bl2[0] = *(const uint32_t*)pbl; bl2[1] = *(const uint32_t*)(pbl + 8);
                mma_f16(sacc[ni], qfh[k16], bh2);
                mma_f16(sacc[ni], qfh[k16], bl2);
                mma_f16(sacc[ni], qfl[k16], bh2);
            }
        }

        // online softmax (rows g and g+8, quad shfl reduce); P stays in regs
        float mx0 = -1e30f, mx1 = -1e30f;
#pragma unroll
        for (int ni = 0; ni < 8; ni++) {
            sacc[ni][0] *= sm_scale; sacc[ni][1] *= sm_scale;
            sacc[ni][2] *= sm_scale; sacc[ni][3] *= sm_scale;
            mx0 = fmaxf(mx0, fmaxf(sacc[ni][0], sacc[ni][1]));
            mx1 = fmaxf(mx1, fmaxf(sacc[ni][2], sacc[ni][3]));
        }
        mx0 = fmaxf(mx0, __shfl_xor_sync(0xffffffffu, mx0, 1));
        mx0 = fmaxf(mx0, __shfl_xor_sync(0xffffffffu, mx0, 2));
        mx1 = fmaxf(mx1, __shfl_xor_sync(0xffffffffu, mx1, 1));
        mx1 = fmaxf(mx1, __shfl_xor_sync(0xffffffffu, mx1, 2));
        float mn0 = fmaxf(m0p, mx0), mn1 = fmaxf(m1p, mx1);
        float a0 = __expf(m0p - mn0), a1 = __expf(m1p - mn1);
        float rs0 = 0.f, rs1 = 0.f;
#pragma unroll
        for (int ni = 0; ni < 8; ni++) {
            sacc[ni][0] = __expf(sacc[ni][0] - mn0);
            sacc[ni][1] = __expf(sacc[ni][1] - mn0);
            sacc[ni][2] = __expf(sacc[ni][2] - mn1);
            sacc[ni][3] = __expf(sacc[ni][3] - mn1);
            rs0 += sacc[ni][0] + sacc[ni][1];
            rs1 += sacc[ni][2] + sacc[ni][3];
        }
        rs0 += __shfl_xor_sync(0xffffffffu, rs0, 1);
        rs0 += __shfl_xor_sync(0xffffffffu, rs0, 2);
        rs1 += __shfl_xor_sync(0xffffffffu, rs1, 1);
        rs1 += __shfl_xor_sync(0xffffffffu, rs1, 2);
        l0 = l0 * a0 + rs0; l1 = l1 * a1 + rs1;
        m0p = mn0; m1p = mn1;

        // rescale O accumulators
#pragma unroll
        for (int ni = 0; ni < 10; ni++) {
            oacc[ni][0] *= a0; oacc[ni][1] *= a0;
            oacc[ni][2] *= a1; oacc[ni][3] *= a1;
        }

        // O += P V: single fp16 MMA (hi only) via C->A fragment reuse
#pragma unroll
        for (int c = 0; c < 4; c++) {
            uint32_t pah[4];
            pah[0] = pack2(sacc[2 * c][0],     sacc[2 * c][1]);
            pah[1] = pack2(sacc[2 * c][2],     sacc[2 * c][3]);
            pah[2] = pack2(sacc[2 * c + 1][0], sacc[2 * c + 1][1]);
            pah[3] = pack2(sacc[2 * c + 1][2], sacc[2 * c + 1][3]);
#pragma unroll
            for (int ni = 0; ni < 10; ni++) {
                const __half* pb = Vsh + (ni * 8 + g) * VSh + c * 16 + q * 2;
                uint32_t bh2[2];
                bh2[0] = *(const uint32_t*)pb;  bh2[1] = *(const uint32_t*)(pb + 8);
                mma_f16(oacc[ni], pah, bh2);
            }
        }
        __syncthreads();
    }

    // normalize + write attn (fp16 hi only) [B,S,D]
    float inv0 = 1.f / l0, inv1 = 1.f / l1;
    int r0 = s0 + wid * 16 + g;
    long o0 = (long)(b * SEQ + r0) * DMODEL + h * HD;
    long o1 = o0 + 8 * DMODEL;
#pragma unroll
    for (int ni = 0; ni < 10; ni++) {
        int col = ni * 8 + 2 * q;
        *(uint32_t*)(g_ah + o0 + col) = pack2(oacc[ni][0] * inv0, oacc[ni][1] * inv0);
        *(uint32_t*)(g_ah + o1 + col) = pack2(oacc[ni][2] * inv1, oacc[ni][3] * inv1);
    }
}

// ============================================================
// launch
// ============================================================
extern "C" void kernel_launch(void* const* d_in, const int* in_sizes, int n_in,
                              void* d_out, int out_size)
{
    const float* x  = (const float*)d_in[0];
    const float* wq = (const float*)d_in[1];
    const float* wk = (const float*)d_in[2];
    const float* wv = (const float*)d_in[3];
    const float* wo = (const float*)d_in[4];
    const float* bo = (const float*)d_in[5];
    const float* qd = (const float*)d_in[6];
    const float* qu = (const float*)d_in[7];
    const float* kd = (const float*)d_in[8];
    const float* ku = (const float*)d_in[9];
    const float* vd = (const float*)d_in[10];
    const float* vu = (const float*)d_in[11];
    const float* od = (const float*)d_in[12];
    const float* ou = (const float*)d_in[13];
    float* out = (float*)d_out;

    cudaFuncSetAttribute(gemm_qkv_mma, cudaFuncAttributeMaxDynamicSharedMemorySize, GEMM_SMEM);
    cudaFuncSetAttribute(gemm_o_mma,   cudaFuncAttributeMaxDynamicSharedMemorySize, GEMM_SMEM);
    cudaFuncSetAttribute(flash_kernel, cudaFuncAttributeMaxDynamicSharedMemorySize, FLASH_SMEM);

    {
        int total = NKV * DMODEL + DMODEL * DMODEL + M_TOT * DMODEL;
        prep_kernel<<<(total + 255) / 256, 256>>>(x, wq, wk, wv, wo,
                                                  qd, qu, kd, ku, vd, vu, od, ou);
    }
    {
        dim3 grid(NKV / 128, M_TOT / 128);   // 15 x 64
        gemm_qkv_mma<<<grid, 256, GEMM_SMEM>>>();
    }
    {
        dim3 grid(SEQ / 64, BATCH * HEADS);  // 32 x 32
        vtrans_kernel<<<grid, 256>>>();
    }
    {
        dim3 grid(SEQ / 64, BATCH * HEADS);  // 32 x 32
        flash_kernel<<<grid, 128, FLASH_SMEM>>>();
    }
    {
        dim3 grid(DMODEL / 128, M_TOT / 128); // 5 x 64
        gemm_o_mma<<<grid, 256, GEMM_SMEM>>>(bo, out);
    }
}